// round 4
// baseline (speedup 1.0000x reference)
#include <cuda_runtime.h>
#include <cuda_bf16.h>
#include <cstdint>
#include <math.h>

#define B_   2
#define S_   2048
#define NH   16
#define DK   64
#define HID  1024
#define ROWS (B_ * S_)          // 4096

static const size_t OUT_ELEMS = (size_t)ROWS * HID;   // 4,194,304

// Scratch (__device__ globals; no allocation allowed)
__device__ float g_Q [(size_t)ROWS * HID];
__device__ float g_K [(size_t)ROWS * HID];
__device__ float g_V [(size_t)ROWS * HID];
__device__ float g_Vt[(size_t)B_ * NH * DK * S_];     // [bh][d][k]
__device__ float g_ctx[(size_t)ROWS * HID];
__device__ float g_tmp[(size_t)ROWS * HID];

// Tile geometry: row = 72 bf16 (144 B) -> conflict-free ldmatrix phases.
#define TROW   72
#define TILE_A_BYTES (128 * TROW * 2)     // 18432
#define SMEM_LIN  (4 * TILE_A_BYTES)      // A0,A1,B0,B1 (128-row B) = 73728
#define SMEM_CTX  (2 * TILE_A_BYTES + 2 * (64 * TROW * 2))  // 55296

// ===========================================================================
// Warp-MMA helpers (sm_80-era PTX: valid on the compute_103 virtual target)
// ===========================================================================
__device__ __forceinline__ uint32_t smem_u32(const void* p) {
    uint32_t a;
    asm("{ .reg .u64 t; cvta.to.shared.u64 t, %1; cvt.u32.u64 %0, t; }"
        : "=r"(a) : "l"(p));
    return a;
}
__device__ __forceinline__ void ldsm_x4(uint32_t (&r)[4], uint32_t addr) {
    asm volatile("ldmatrix.sync.aligned.m8n8.x4.shared.b16 {%0,%1,%2,%3}, [%4];"
                 : "=r"(r[0]), "=r"(r[1]), "=r"(r[2]), "=r"(r[3]) : "r"(addr));
}
__device__ __forceinline__ void mma16816(float (&c)[4], const uint32_t (&a)[4],
                                         uint32_t b0, uint32_t b1) {
    asm volatile(
        "mma.sync.aligned.m16n8k16.row.col.f32.bf16.bf16.f32 "
        "{%0,%1,%2,%3}, {%4,%5,%6,%7}, {%8,%9}, {%0,%1,%2,%3};"
        : "+f"(c[0]), "+f"(c[1]), "+f"(c[2]), "+f"(c[3])
        : "r"(a[0]), "r"(a[1]), "r"(a[2]), "r"(a[3]), "r"(b0), "r"(b1));
}

// 2-term bf16 split of a float pair, packed little-endian
__device__ __forceinline__ void split2(float x, float y, uint32_t& hi, uint32_t& lo) {
    __nv_bfloat16 hx = __float2bfloat16(x);
    __nv_bfloat16 hy = __float2bfloat16(y);
    __nv_bfloat16 lx = __float2bfloat16(x - __bfloat162float(hx));
    __nv_bfloat16 ly = __float2bfloat16(y - __bfloat162float(hy));
    hi = (uint32_t)__bfloat16_as_ushort(hx) | ((uint32_t)__bfloat16_as_ushort(hy) << 16);
    lo = (uint32_t)__bfloat16_as_ushort(lx) | ((uint32_t)__bfloat16_as_ushort(ly) << 16);
}
// Store 4 source floats at tile (row, c..c+3): hi at cols c, lo at cols c+32.
__device__ __forceinline__ void sts_f4(__nv_bfloat16 (*T)[TROW], int row, int c, float4 v) {
    uint32_t h0, l0, h1, l1;
    split2(v.x, v.y, h0, l0);
    split2(v.z, v.w, h1, l1);
    uint32_t* p = (uint32_t*)&T[row][c];
    p[0] = h0; p[1] = h1;
    uint32_t* q = (uint32_t*)&T[row][c + 32];
    q[0] = l0; q[1] = l1;
}

// One K-chunk (32 source floats = 2 k16 steps), warp tile 32 x (NT*8).
// B fragments fetched via ldmatrix.x4 (two n-tiles per load).
template <int NT>
__device__ __forceinline__ void mma_chunk(float (*cacc)[NT][4],
                                          const __nv_bfloat16 (*As)[TROW],
                                          const __nv_bfloat16 (*Bs)[TROW],
                                          int wm, int wn, int lane) {
#pragma unroll
    for (int s = 0; s < 2; s++) {
        uint32_t ah[2][4], al[2][4];
#pragma unroll
        for (int mt = 0; mt < 2; mt++) {
            const int r = wm * 32 + mt * 16 + (lane & 15);
            const int cc = s * 16 + ((lane >> 4) << 3);
            ldsm_x4(ah[mt], smem_u32(&As[r][cc]));
            ldsm_x4(al[mt], smem_u32(&As[r][cc + 32]));
        }
#pragma unroll
        for (int g = 0; g < NT / 2; g++) {
            const int br = wn * (NT * 8) + g * 16 + (lane & 15);
            const int bc = s * 16 + ((lane >> 4) << 3);
            uint32_t bh[4], bl[4];
            ldsm_x4(bh, smem_u32(&Bs[br][bc]));       // {n0-7 kLo, n8-15 kLo, n0-7 kHi, n8-15 kHi}
            ldsm_x4(bl, smem_u32(&Bs[br][bc + 32]));
#pragma unroll
            for (int mt = 0; mt < 2; mt++) {
                mma16816(cacc[mt][2 * g],     ah[mt], bh[0], bh[2]);
                mma16816(cacc[mt][2 * g],     ah[mt], bl[0], bl[2]);
                mma16816(cacc[mt][2 * g],     al[mt], bh[0], bh[2]);
                mma16816(cacc[mt][2 * g + 1], ah[mt], bh[1], bh[3]);
                mma16816(cacc[mt][2 * g + 1], ah[mt], bl[1], bl[3]);
                mma16816(cacc[mt][2 * g + 1], al[mt], bh[1], bh[3]);
            }
        }
    }
}

// ===========================================================================
// Linear: C[128x128 tile] = A @ B^T (+res). K=1024. Double-buffered mainloop.
// ===========================================================================
__device__ __forceinline__ void lin_body(const float* __restrict__ A,
                                         const float* __restrict__ Bw,
                                         float* __restrict__ C,
                                         const float* __restrict__ res) {
    extern __shared__ __align__(16) char sm[];
    __nv_bfloat16 (*As[2])[TROW] = {(__nv_bfloat16(*)[TROW])sm,
                                    (__nv_bfloat16(*)[TROW])(sm + TILE_A_BYTES)};
    __nv_bfloat16 (*Bs[2])[TROW] = {(__nv_bfloat16(*)[TROW])(sm + 2 * TILE_A_BYTES),
                                    (__nv_bfloat16(*)[TROW])(sm + 3 * TILE_A_BYTES)};
    const int tid = threadIdx.x, lane = tid & 31, wid = tid >> 5;
    const int wm = wid & 3, wn = wid >> 2;
    const int rowBase = blockIdx.y * 128, colBase = blockIdx.x * 128;
    const int lr = tid >> 1, c0 = (tid & 1) * 16;
    const float* Ar = A + (size_t)(rowBase + lr) * HID + c0;
    const float* Br = Bw + (size_t)(colBase + lr) * HID + c0;

    float c[2][8][4] = {};
    float4 ra[4], rb[4];
#pragma unroll
    for (int i = 0; i < 4; i++) {
        ra[i] = *(const float4*)(Ar + i * 4);
        rb[i] = *(const float4*)(Br + i * 4);
    }
#pragma unroll
    for (int i = 0; i < 4; i++) {
        sts_f4(As[0], lr, c0 + i * 4, ra[i]);
        sts_f4(Bs[0], lr, c0 + i * 4, rb[i]);
    }
    __syncthreads();
    for (int ch = 0; ch < 32; ch++) {
        const int cur = ch & 1;
        if (ch < 31) {
            const float* An = Ar + (ch + 1) * 32;
            const float* Bn = Br + (ch + 1) * 32;
#pragma unroll
            for (int i = 0; i < 4; i++) {
                ra[i] = *(const float4*)(An + i * 4);
                rb[i] = *(const float4*)(Bn + i * 4);
            }
        }
        mma_chunk<8>(c, As[cur], Bs[cur], wm, wn, lane);
        if (ch < 31) {
#pragma unroll
            for (int i = 0; i < 4; i++) {
                sts_f4(As[cur ^ 1], lr, c0 + i * 4, ra[i]);
                sts_f4(Bs[cur ^ 1], lr, c0 + i * 4, rb[i]);
            }
            __syncthreads();
        }
    }
#pragma unroll
    for (int mt = 0; mt < 2; mt++) {
        const int r0 = rowBase + wm * 32 + mt * 16 + (lane >> 2);
#pragma unroll
        for (int nt = 0; nt < 8; nt++) {
            const int cc = colBase + wn * 64 + nt * 8 + (lane & 3) * 2;
            float2 v0 = make_float2(c[mt][nt][0], c[mt][nt][1]);
            float2 v1 = make_float2(c[mt][nt][2], c[mt][nt][3]);
            if (res) {
                float2 q0 = *(const float2*)(res + (size_t)r0 * HID + cc);
                float2 q1 = *(const float2*)(res + (size_t)(r0 + 8) * HID + cc);
                v0.x += q0.x; v0.y += q0.y;
                v1.x += q1.x; v1.y += q1.y;
            }
            *(float2*)(C + (size_t)r0 * HID + cc) = v0;
            *(float2*)(C + (size_t)(r0 + 8) * HID + cc) = v1;
        }
    }
}

__global__ __launch_bounds__(256) void tc_proj_qkv(const float* __restrict__ X,
                                                   const float* __restrict__ Wq,
                                                   const float* __restrict__ Wk,
                                                   const float* __restrict__ Wv) {
    const int z = blockIdx.z;
    const float* W = (z == 0) ? Wq : (z == 1) ? Wk : Wv;
    float* C = (z == 0) ? g_Q : (z == 1) ? g_K : g_V;
    lin_body(X, W, C, nullptr);
}
__global__ __launch_bounds__(256) void tc_oproj(const float* __restrict__ Wo,
                                                const float* __restrict__ X) {
    lin_body(g_ctx, Wo, g_tmp, X);
}

// ===========================================================================
// Scores: attn_raw = (Q_h @ K_h^T)/8, masked -> -1e9.  grid (16,16,32)
// ===========================================================================
__global__ __launch_bounds__(256) void tc_scores(const int* __restrict__ mask,
                                                 float* __restrict__ attn) {
    extern __shared__ __align__(16) char sm[];
    __nv_bfloat16 (*As[2])[TROW] = {(__nv_bfloat16(*)[TROW])sm,
                                    (__nv_bfloat16(*)[TROW])(sm + TILE_A_BYTES)};
    __nv_bfloat16 (*Bs[2])[TROW] = {(__nv_bfloat16(*)[TROW])(sm + 2 * TILE_A_BYTES),
                                    (__nv_bfloat16(*)[TROW])(sm + 3 * TILE_A_BYTES)};
    const int tid = threadIdx.x, lane = tid & 31, wid = tid >> 5;
    const int wm = wid & 3, wn = wid >> 2;
    const int bh = blockIdx.z, b = bh >> 4, h = bh & 15;
    const int rowBase = blockIdx.y * 128, colBase = blockIdx.x * 128;
    const int lr = tid >> 1, c0 = (tid & 1) * 16;
    const size_t hoff = (size_t)b * S_ * HID + (size_t)h * DK;
    const float* Ar = g_Q + hoff + (size_t)(rowBase + lr) * HID + c0;
    const float* Br = g_K + hoff + (size_t)(colBase + lr) * HID + c0;

    float c[2][8][4] = {};
    float4 ra[4], rb[4];
#pragma unroll
    for (int i = 0; i < 4; i++) {
        ra[i] = *(const float4*)(Ar + i * 4);
        rb[i] = *(const float4*)(Br + i * 4);
    }
#pragma unroll
    for (int i = 0; i < 4; i++) {
        sts_f4(As[0], lr, c0 + i * 4, ra[i]);
        sts_f4(Bs[0], lr, c0 + i * 4, rb[i]);
    }
    __syncthreads();
    for (int ch = 0; ch < 2; ch++) {          // K = 64
        const int cur = ch & 1;
        if (ch < 1) {
#pragma unroll
            for (int i = 0; i < 4; i++) {
                ra[i] = *(const float4*)(Ar + 32 + i * 4);
                rb[i] = *(const float4*)(Br + 32 + i * 4);
            }
        }
        mma_chunk<8>(c, As[cur], Bs[cur], wm, wn, lane);
        if (ch < 1) {
#pragma unroll
            for (int i = 0; i < 4; i++) {
                sts_f4(As[cur ^ 1], lr, c0 + i * 4, ra[i]);
                sts_f4(Bs[cur ^ 1], lr, c0 + i * 4, rb[i]);
            }
            __syncthreads();
        }
    }
    const int* mb = mask + (size_t)b * S_ * S_;
    float* ab = attn + (size_t)bh * S_ * S_;
#pragma unroll
    for (int mt = 0; mt < 2; mt++) {
        const int r0 = rowBase + wm * 32 + mt * 16 + (lane >> 2);
#pragma unroll
        for (int nt = 0; nt < 8; nt++) {
            const int cc = colBase + wn * 64 + nt * 8 + (lane & 3) * 2;
            int2 m0 = *(const int2*)(mb + (size_t)r0 * S_ + cc);
            int2 m1 = *(const int2*)(mb + (size_t)(r0 + 8) * S_ + cc);
            float2 v0, v1;
            v0.x = m0.x ? c[mt][nt][0] * 0.125f : -1e9f;
            v0.y = m0.y ? c[mt][nt][1] * 0.125f : -1e9f;
            v1.x = m1.x ? c[mt][nt][2] * 0.125f : -1e9f;
            v1.y = m1.y ? c[mt][nt][3] * 0.125f : -1e9f;
            *(float2*)(ab + (size_t)r0 * S_ + cc) = v0;
            *(float2*)(ab + (size_t)(r0 + 8) * S_ + cc) = v1;
        }
    }
}

// ===========================================================================
// Context: ctx[q,d] = sum_k attn[q,k] * Vt[bh][d][k].  N=64, warp tile 32x32.
// ===========================================================================
__global__ __launch_bounds__(256) void tc_context(const float* __restrict__ attn) {
    extern __shared__ __align__(16) char sm[];
    __nv_bfloat16 (*As[2])[TROW] = {(__nv_bfloat16(*)[TROW])sm,
                                    (__nv_bfloat16(*)[TROW])(sm + TILE_A_BYTES)};
    __nv_bfloat16 (*Bs[2])[TROW] = {(__nv_bfloat16(*)[TROW])(sm + 2 * TILE_A_BYTES),
                                    (__nv_bfloat16(*)[TROW])(sm + 2 * TILE_A_BYTES + 64 * TROW * 2)};
    const int tid = threadIdx.x, lane = tid & 31, wid = tid >> 5;
    const int wm = wid & 3, wn = wid >> 2;
    const int bh = blockIdx.z, b = bh >> 4, h = bh & 15;
    const int rowBase = blockIdx.x * 128;
    const int lr = tid >> 1, c0 = (tid & 1) * 16;       // A loader: 2 thr/row
    const int brow = tid >> 2, bc0 = (tid & 3) * 8;     // B loader: 4 thr/row
    const float* Ar = attn + (size_t)bh * S_ * S_ + (size_t)(rowBase + lr) * S_ + c0;
    const float* Br = g_Vt + (size_t)bh * DK * S_ + (size_t)brow * S_ + bc0;

    float c[2][4][4] = {};
    float4 ra[4], rb[2];
#pragma unroll
    for (int i = 0; i < 4; i++) ra[i] = *(const float4*)(Ar + i * 4);
    rb[0] = *(const float4*)(Br);
    rb[1] = *(const float4*)(Br + 4);
#pragma unroll
    for (int i = 0; i < 4; i++) sts_f4(As[0], lr, c0 + i * 4, ra[i]);
    sts_f4(Bs[0], brow, bc0, rb[0]);
    sts_f4(Bs[0], brow, bc0 + 4, rb[1]);
    __syncthreads();
    for (int ch = 0; ch < 64; ch++) {         // K = 2048
        const int cur = ch & 1;
        if (ch < 63) {
            const float* An = Ar + (ch + 1) * 32;
            const float* Bn = Br + (ch + 1) * 32;
#pragma unroll
            for (int i = 0; i < 4; i++) ra[i] = *(const float4*)(An + i * 4);
            rb[0] = *(const float4*)(Bn);
            rb[1] = *(const float4*)(Bn + 4);
        }
        mma_chunk<4>(c, As[cur], Bs[cur], wm, wn, lane);
        if (ch < 63) {
#pragma unroll
            for (int i = 0; i < 4; i++) sts_f4(As[cur ^ 1], lr, c0 + i * 4, ra[i]);
            sts_f4(Bs[cur ^ 1], brow, bc0, rb[0]);
            sts_f4(Bs[cur ^ 1], brow, bc0 + 4, rb[1]);
            __syncthreads();
        }
    }
#pragma unroll
    for (int mt = 0; mt < 2; mt++) {
        const int q0 = rowBase + wm * 32 + mt * 16 + (lane >> 2);
#pragma unroll
        for (int nt = 0; nt < 4; nt++) {
            const int d = wn * 32 + nt * 8 + (lane & 3) * 2;
            float* p0 = g_ctx + ((size_t)b * S_ + q0) * HID + (size_t)h * DK + d;
            float* p1 = g_ctx + ((size_t)b * S_ + q0 + 8) * HID + (size_t)h * DK + d;
            *(float2*)p0 = make_float2(c[mt][nt][0], c[mt][nt][1]);
            *(float2*)p1 = make_float2(c[mt][nt][2], c[mt][nt][3]);
        }
    }
}

// ===========================================================================
// V transpose: g_Vt[bh][d][k] = g_V[(b*S+k)*HID + h*64 + d]
// ===========================================================================
__global__ void vtrans_kernel() {
    __shared__ float ts[32][33];
    const int bh = blockIdx.z, b = bh >> 4, h = bh & 15;
    const int k0 = blockIdx.x * 32, d0 = blockIdx.y * 32;
    const int tx = threadIdx.x, ty = threadIdx.y;
#pragma unroll
    for (int i = 0; i < 4; i++) {
        int k = k0 + ty + i * 8;
        ts[ty + i * 8][tx] = g_V[((size_t)b * S_ + k) * HID + (size_t)h * DK + d0 + tx];
    }
    __syncthreads();
#pragma unroll
    for (int i = 0; i < 4; i++) {
        int d = d0 + ty + i * 8;
        g_Vt[(size_t)bh * DK * S_ + (size_t)d * S_ + k0 + tx] = ts[tx][ty + i * 8];
    }
}

// ===========================================================================
// Softmax + LayerNorm
// ===========================================================================
__device__ __forceinline__ float blockReduceMax(float v) {
    __shared__ float s[8];
    const int lane = threadIdx.x & 31, wid = threadIdx.x >> 5;
#pragma unroll
    for (int o = 16; o > 0; o >>= 1) v = fmaxf(v, __shfl_xor_sync(0xffffffffu, v, o));
    __syncthreads();
    if (lane == 0) s[wid] = v;
    __syncthreads();
    float r = s[0];
#pragma unroll
    for (int i = 1; i < 8; i++) r = fmaxf(r, s[i]);
    return r;
}
__device__ __forceinline__ float blockReduceSum(float v) {
    __shared__ float s[8];
    const int lane = threadIdx.x & 31, wid = threadIdx.x >> 5;
#pragma unroll
    for (int o = 16; o > 0; o >>= 1) v += __shfl_xor_sync(0xffffffffu, v, o);
    __syncthreads();
    if (lane == 0) s[wid] = v;
    __syncthreads();
    float r = s[0];
#pragma unroll
    for (int i = 1; i < 8; i++) r += s[i];
    return r;
}

__global__ __launch_bounds__(256) void softmax_kernel(float* __restrict__ attn) {
    const size_t row = blockIdx.x;
    float4* p = (float4*)(attn + row * (size_t)S_);
    const int tid = threadIdx.x;
    float4 v0 = p[tid];
    float4 v1 = p[tid + 256];
    float m = fmaxf(fmaxf(fmaxf(v0.x, v0.y), fmaxf(v0.z, v0.w)),
                    fmaxf(fmaxf(v1.x, v1.y), fmaxf(v1.z, v1.w)));
    m = blockReduceMax(m);
    float4 e0, e1;
    e0.x = __expf(v0.x - m); e0.y = __expf(v0.y - m);
    e0.z = __expf(v0.z - m); e0.w = __expf(v0.w - m);
    e1.x = __expf(v1.x - m); e1.y = __expf(v1.y - m);
    e1.z = __expf(v1.z - m); e1.w = __expf(v1.w - m);
    float s = e0.x + e0.y + e0.z + e0.w + e1.x + e1.y + e1.z + e1.w;
    s = blockReduceSum(s);
    float inv = 1.0f / s;
    e0.x *= inv; e0.y *= inv; e0.z *= inv; e0.w *= inv;
    e1.x *= inv; e1.y *= inv; e1.z *= inv; e1.w *= inv;
    p[tid] = e0;
    p[tid + 256] = e1;
}

__global__ __launch_bounds__(256) void ln_kernel(const float* __restrict__ x,
                                                 float* __restrict__ out) {
    const size_t row = blockIdx.x;
    const float4* p = (const float4*)(x + row * HID);
    const int tid = threadIdx.x;
    float4 v = p[tid];
    float s = v.x + v.y + v.z + v.w;
    s = blockReduceSum(s);
    const float mu = s * (1.0f / HID);
    float dx = v.x - mu, dy = v.y - mu, dz = v.z - mu, dw = v.w - mu;
    float sq = dx * dx + dy * dy + dz * dz + dw * dw;
    sq = blockReduceSum(sq);
    const float inv = rsqrtf(sq * (1.0f / HID) + 1e-5f);
    float4 o;
    o.x = dx * inv; o.y = dy * inv; o.z = dz * inv; o.w = dw * inv;
    ((float4*)(out + row * HID))[tid] = o;
}

// ===========================================================================
extern "C" void kernel_launch(void* const* d_in, const int* in_sizes, int n_in,
                              void* d_out, int out_size)
{
    (void)in_sizes; (void)n_in; (void)out_size;
    const float* x  = (const float*)d_in[0];
    const int* mask = (const int*)d_in[1];
    const float* Wq = (const float*)d_in[2];
    const float* Wk = (const float*)d_in[3];
    const float* Wv = (const float*)d_in[4];
    const float* Wo = (const float*)d_in[5];
    float* out  = (float*)d_out;
    float* attn = out + OUT_ELEMS;

    float* gtmp;
    cudaGetSymbolAddress((void**)&gtmp, g_tmp);

    // Dynamic-smem opt-in (host attribute set; idempotent, capture-safe)
    cudaFuncSetAttribute(tc_proj_qkv, cudaFuncAttributeMaxDynamicSharedMemorySize, SMEM_LIN);
    cudaFuncSetAttribute(tc_oproj,    cudaFuncAttributeMaxDynamicSharedMemorySize, SMEM_LIN);
    cudaFuncSetAttribute(tc_scores,   cudaFuncAttributeMaxDynamicSharedMemorySize, SMEM_LIN);
    cudaFuncSetAttribute(tc_context,  cudaFuncAttributeMaxDynamicSharedMemorySize, SMEM_CTX);

    dim3 blk(256);

    // Q/K/V projections (split-bf16 HMMA), batched over z
    tc_proj_qkv<<<dim3(HID / 128, ROWS / 128, 3), blk, SMEM_LIN>>>(x, Wq, Wk, Wv);

    // V -> Vt (K-major per head)
    vtrans_kernel<<<dim3(S_ / 32, DK / 32, B_ * NH), dim3(32, 8)>>>();

    // Masked scaled raw scores
    tc_scores<<<dim3(S_ / 128, S_ / 128, B_ * NH), blk, SMEM_LIN>>>(mask, attn);

    // Row softmax in place
    softmax_kernel<<<dim3(B_ * NH * S_), blk>>>(attn);

    // context = attn @ V_head
    tc_context<<<dim3(S_ / 128, 1, B_ * NH), blk, SMEM_CTX>>>(attn);

    // Output projection + residual
    tc_oproj<<<dim3(HID / 128, ROWS / 128), blk, SMEM_LIN>>>(Wo, x);

    // LayerNorm -> final output
    ln_kernel<<<dim3(ROWS), blk>>>(gtmp, out);
}

// round 5
// speedup vs baseline: 1.4187x; 1.4187x over previous
#include <cuda_runtime.h>
#include <cuda_bf16.h>
#include <cstdint>
#include <math.h>

#define B_   2
#define S_   2048
#define NH   16
#define DK   64
#define HID  1024
#define ROWS (B_ * S_)          // 4096

static const size_t OUT_ELEMS = (size_t)ROWS * HID;   // 4,194,304

// ---------------------------------------------------------------------------
// Scratch (__device__ globals; no allocation allowed)
// ---------------------------------------------------------------------------
__device__ __nv_bfloat16 g_Xh [(size_t)ROWS * HID];
__device__ __nv_bfloat16 g_Xl [(size_t)ROWS * HID];
__device__ __nv_bfloat16 g_Wqh[(size_t)HID * HID];
__device__ __nv_bfloat16 g_Wql[(size_t)HID * HID];
__device__ __nv_bfloat16 g_Wkh[(size_t)HID * HID];
__device__ __nv_bfloat16 g_Wkl[(size_t)HID * HID];
__device__ __nv_bfloat16 g_Wvh[(size_t)HID * HID];
__device__ __nv_bfloat16 g_Woh[(size_t)HID * HID];
__device__ __nv_bfloat16 g_Qh [(size_t)ROWS * HID];
__device__ __nv_bfloat16 g_Ql [(size_t)ROWS * HID];
__device__ __nv_bfloat16 g_Kh [(size_t)ROWS * HID];
__device__ __nv_bfloat16 g_Kl [(size_t)ROWS * HID];
__device__ __nv_bfloat16 g_Vt16[(size_t)B_ * NH * DK * S_];          // [bh][d][k]
__device__ __nv_bfloat16 g_attn16[(size_t)B_ * NH * S_ * S_];        // 268 MB
__device__ __nv_bfloat16 g_ctx16[(size_t)ROWS * HID];
__device__ float         g_tmp [(size_t)ROWS * HID];

// Tile geometry: row = 72 bf16 (144 B) -> conflict-free ldmatrix phases.
#define TROW    72
#define TILE128 (128 * TROW * 2)   // 18432
#define TILE64  (64 * TROW * 2)    // 9216
#define SMEM_GEMM (4 * TILE128)                 // 73728: A0,A1,B0,B1
#define SMEM_CTX  (2 * TILE128 + 2 * TILE64)    // 55296

// ---------------------------------------------------------------------------
// PTX helpers
// ---------------------------------------------------------------------------
__device__ __forceinline__ uint32_t smem_u32(const void* p) {
    uint32_t a;
    asm("{ .reg .u64 t; cvta.to.shared.u64 t, %1; cvt.u32.u64 %0, t; }"
        : "=r"(a) : "l"(p));
    return a;
}
__device__ __forceinline__ void cpa16(uint32_t dst, const __nv_bfloat16* src) {
    asm volatile("cp.async.cg.shared.global [%0], [%1], 16;"
                 :: "r"(dst), "l"(__cvta_generic_to_global(src)));
}
#define CPCOMMIT() asm volatile("cp.async.commit_group;" ::: "memory")
#define CPWAIT1()  asm volatile("cp.async.wait_group 1;" ::: "memory")
#define CPWAIT0()  asm volatile("cp.async.wait_group 0;" ::: "memory")

__device__ __forceinline__ void ldsm_x4(uint32_t (&r)[4], uint32_t addr) {
    asm volatile("ldmatrix.sync.aligned.m8n8.x4.shared.b16 {%0,%1,%2,%3}, [%4];"
                 : "=r"(r[0]), "=r"(r[1]), "=r"(r[2]), "=r"(r[3]) : "r"(addr));
}
__device__ __forceinline__ void mma16816(float (&c)[4], const uint32_t (&a)[4],
                                         uint32_t b0, uint32_t b1) {
    asm volatile(
        "mma.sync.aligned.m16n8k16.row.col.f32.bf16.bf16.f32 "
        "{%0,%1,%2,%3}, {%4,%5,%6,%7}, {%8,%9}, {%0,%1,%2,%3};"
        : "+f"(c[0]), "+f"(c[1]), "+f"(c[2]), "+f"(c[3])
        : "r"(a[0]), "r"(a[1]), "r"(a[2]), "r"(a[3]), "r"(b0), "r"(b1));
}

// One K-chunk of MMAs.  SPLIT: cols [0..31]=hi, [32..63]=lo, 2 k16 steps,
// terms hi*hi + hi*lo + lo*hi.  PLAIN: cols [0..63], 4 k16 steps, 1 term.
template <int NT, bool SPLIT>
__device__ __forceinline__ void mma_chunk(float (*cacc)[NT][4],
                                          const __nv_bfloat16 (*As)[TROW],
                                          const __nv_bfloat16 (*Bs)[TROW],
                                          int wm, int wn, int lane) {
    const int NS = SPLIT ? 2 : 4;
#pragma unroll
    for (int s = 0; s < NS; s++) {
        uint32_t ah[2][4], al[2][4];
#pragma unroll
        for (int mt = 0; mt < 2; mt++) {
            const int r = wm * 32 + mt * 16 + (lane & 15);
            const int cc = s * 16 + ((lane >> 4) << 3);
            ldsm_x4(ah[mt], smem_u32(&As[r][cc]));
            if (SPLIT) ldsm_x4(al[mt], smem_u32(&As[r][cc + 32]));
        }
#pragma unroll
        for (int g = 0; g < NT / 2; g++) {
            const int br = wn * (NT * 8) + g * 16 + (lane & 15);
            const int bc = s * 16 + ((lane >> 4) << 3);
            uint32_t bh[4], bl[4];
            ldsm_x4(bh, smem_u32(&Bs[br][bc]));
            if (SPLIT) ldsm_x4(bl, smem_u32(&Bs[br][bc + 32]));
#pragma unroll
            for (int mt = 0; mt < 2; mt++) {
                mma16816(cacc[mt][2 * g],     ah[mt], bh[0], bh[2]);
                mma16816(cacc[mt][2 * g + 1], ah[mt], bh[1], bh[3]);
                if (SPLIT) {
                    mma16816(cacc[mt][2 * g],     ah[mt], bl[0], bl[2]);
                    mma16816(cacc[mt][2 * g + 1], ah[mt], bl[1], bl[3]);
                    mma16816(cacc[mt][2 * g],     al[mt], bh[0], bh[2]);
                    mma16816(cacc[mt][2 * g + 1], al[mt], bh[1], bh[3]);
                }
            }
        }
    }
}

// ---------------------------------------------------------------------------
// Conversion kernels: f32 -> bf16 hi (+ optional lo), 4 elements per thread
// ---------------------------------------------------------------------------
__global__ __launch_bounds__(256) void k_cvt(const float* __restrict__ s,
                                             __nv_bfloat16* __restrict__ dh,
                                             __nv_bfloat16* __restrict__ dl,
                                             int n4) {
    const int i = blockIdx.x * 256 + threadIdx.x;
    if (i >= n4) return;
    float4 v = ((const float4*)s)[i];
    __nv_bfloat16 h0 = __float2bfloat16(v.x), h1 = __float2bfloat16(v.y);
    __nv_bfloat16 h2 = __float2bfloat16(v.z), h3 = __float2bfloat16(v.w);
    uint2 hw;
    hw.x = (uint32_t)__bfloat16_as_ushort(h0) | ((uint32_t)__bfloat16_as_ushort(h1) << 16);
    hw.y = (uint32_t)__bfloat16_as_ushort(h2) | ((uint32_t)__bfloat16_as_ushort(h3) << 16);
    *(uint2*)(dh + (size_t)i * 4) = hw;
    if (dl) {
        __nv_bfloat16 l0 = __float2bfloat16(v.x - __bfloat162float(h0));
        __nv_bfloat16 l1 = __float2bfloat16(v.y - __bfloat162float(h1));
        __nv_bfloat16 l2 = __float2bfloat16(v.z - __bfloat162float(h2));
        __nv_bfloat16 l3 = __float2bfloat16(v.w - __bfloat162float(h3));
        uint2 lw;
        lw.x = (uint32_t)__bfloat16_as_ushort(l0) | ((uint32_t)__bfloat16_as_ushort(l1) << 16);
        lw.y = (uint32_t)__bfloat16_as_ushort(l2) | ((uint32_t)__bfloat16_as_ushort(l3) << 16);
        *(uint2*)(dl + (size_t)i * 4) = lw;
    }
}

// ---------------------------------------------------------------------------
// Q/K projection (split): C = X @ W^T, epilogue splits result to hi/lo bf16.
// grid (8, 32, 2): z=0 -> Q, z=1 -> K.
// ---------------------------------------------------------------------------
__global__ __launch_bounds__(256) void k_proj_qk() {
    extern __shared__ __align__(16) char sm[];
    const int tid = threadIdx.x, lane = tid & 31, wid = tid >> 5;
    const int wm = wid & 3, wn = wid >> 2;
    const int z = blockIdx.z;
    const int rowBase = blockIdx.y * 128, colBase = blockIdx.x * 128;
    const __nv_bfloat16* Bh = z ? g_Wkh : g_Wqh;
    const __nv_bfloat16* Bl = z ? g_Wkl : g_Wql;
    __nv_bfloat16* Oh = z ? g_Kh : g_Qh;
    __nv_bfloat16* Ol = z ? g_Kl : g_Ql;

    const int lrow = tid >> 1, hl = tid & 1;
    const __nv_bfloat16* asrc = (hl ? g_Xl : g_Xh) + (size_t)(rowBase + lrow) * HID;
    const __nv_bfloat16* bsrc = (hl ? Bl : Bh) + (size_t)(colBase + lrow) * HID;
    const uint32_t sb = smem_u32(sm);
    const uint32_t adst = sb + lrow * 144 + hl * 64;
    const uint32_t bdst = sb + 2 * TILE128 + lrow * 144 + hl * 64;

    // prologue
#pragma unroll
    for (int i = 0; i < 4; i++) {
        cpa16(adst + i * 16, asrc + i * 8);
        cpa16(bdst + i * 16, bsrc + i * 8);
    }
    CPCOMMIT();

    float c[2][8][4] = {};
    for (int ch = 0; ch < 32; ch++) {
        const int cur = ch & 1;
        if (ch < 31) {
            const int nb = cur ^ 1;
            const __nv_bfloat16* a = asrc + (ch + 1) * 32;
            const __nv_bfloat16* b = bsrc + (ch + 1) * 32;
#pragma unroll
            for (int i = 0; i < 4; i++) {
                cpa16(adst + nb * TILE128 + i * 16, a + i * 8);
                cpa16(bdst + nb * TILE128 + i * 16, b + i * 8);
            }
            CPCOMMIT();
            CPWAIT1();
        } else {
            CPWAIT0();
        }
        __syncthreads();
        mma_chunk<8, true>(c, (const __nv_bfloat16(*)[TROW])(sm + cur * TILE128),
                           (const __nv_bfloat16(*)[TROW])(sm + (2 + cur) * TILE128),
                           wm, wn, lane);
        __syncthreads();
    }
#pragma unroll
    for (int mt = 0; mt < 2; mt++) {
#pragma unroll
        for (int half = 0; half < 2; half++) {
            const int r = rowBase + wm * 32 + mt * 16 + (lane >> 2) + half * 8;
#pragma unroll
            for (int nt = 0; nt < 8; nt++) {
                const int cc = colBase + wn * 64 + nt * 8 + (lane & 3) * 2;
                float v0 = c[mt][nt][half * 2], v1 = c[mt][nt][half * 2 + 1];
                __nv_bfloat16 h0 = __float2bfloat16(v0), h1 = __float2bfloat16(v1);
                __nv_bfloat16 l0 = __float2bfloat16(v0 - __bfloat162float(h0));
                __nv_bfloat16 l1 = __float2bfloat16(v1 - __bfloat162float(h1));
                uint32_t hw = (uint32_t)__bfloat16_as_ushort(h0) |
                              ((uint32_t)__bfloat16_as_ushort(h1) << 16);
                uint32_t lw = (uint32_t)__bfloat16_as_ushort(l0) |
                              ((uint32_t)__bfloat16_as_ushort(l1) << 16);
                *(uint32_t*)(Oh + (size_t)r * HID + cc) = hw;
                *(uint32_t*)(Ol + (size_t)r * HID + cc) = lw;
            }
        }
    }
}

// ---------------------------------------------------------------------------
// V projection (plain bf16): V = X @ Wv^T, epilogue scatters into Vt16[bh][d][k]
// grid (8, 32)
// ---------------------------------------------------------------------------
__global__ __launch_bounds__(256) void k_proj_v() {
    extern __shared__ __align__(16) char sm[];
    const int tid = threadIdx.x, lane = tid & 31, wid = tid >> 5;
    const int wm = wid & 3, wn = wid >> 2;
    const int rowBase = blockIdx.y * 128, colBase = blockIdx.x * 128;

    const int lrow = tid >> 1, hf = tid & 1;
    const __nv_bfloat16* asrc = g_Xh + (size_t)(rowBase + lrow) * HID + hf * 32;
    const __nv_bfloat16* bsrc = g_Wvh + (size_t)(colBase + lrow) * HID + hf * 32;
    const uint32_t sb = smem_u32(sm);
    const uint32_t adst = sb + lrow * 144 + hf * 64;
    const uint32_t bdst = sb + 2 * TILE128 + lrow * 144 + hf * 64;

#pragma unroll
    for (int i = 0; i < 4; i++) {
        cpa16(adst + i * 16, asrc + i * 8);
        cpa16(bdst + i * 16, bsrc + i * 8);
    }
    CPCOMMIT();

    float c[2][8][4] = {};
    for (int ch = 0; ch < 16; ch++) {        // K = 1024, chunk 64
        const int cur = ch & 1;
        if (ch < 15) {
            const int nb = cur ^ 1;
            const __nv_bfloat16* a = asrc + (ch + 1) * 64;
            const __nv_bfloat16* b = bsrc + (ch + 1) * 64;
#pragma unroll
            for (int i = 0; i < 4; i++) {
                cpa16(adst + nb * TILE128 + i * 16, a + i * 8);
                cpa16(bdst + nb * TILE128 + i * 16, b + i * 8);
            }
            CPCOMMIT();
            CPWAIT1();
        } else {
            CPWAIT0();
        }
        __syncthreads();
        mma_chunk<8, false>(c, (const __nv_bfloat16(*)[TROW])(sm + cur * TILE128),
                            (const __nv_bfloat16(*)[TROW])(sm + (2 + cur) * TILE128),
                            wm, wn, lane);
        __syncthreads();
    }
    // scatter to Vt16[bh][d][k]
#pragma unroll
    for (int mt = 0; mt < 2; mt++) {
#pragma unroll
        for (int half = 0; half < 2; half++) {
            const int r = rowBase + wm * 32 + mt * 16 + (lane >> 2) + half * 8;
            const int b = r >> 11, k = r & (S_ - 1);
#pragma unroll
            for (int nt = 0; nt < 8; nt++) {
                const int cc = colBase + wn * 64 + nt * 8 + (lane & 3) * 2;
                const int h = cc >> 6, d = cc & 63;
                const size_t base = ((size_t)(b * NH + h) * DK + d) * S_ + k;
                g_Vt16[base]      = __float2bfloat16(c[mt][nt][half * 2]);
                g_Vt16[base + S_] = __float2bfloat16(c[mt][nt][half * 2 + 1]);
            }
        }
    }
}

// ---------------------------------------------------------------------------
// Scores (split): raw = (Q_h @ K_h^T)/8, masked -> -1e9.  grid (16,16,32)
// ---------------------------------------------------------------------------
__global__ __launch_bounds__(256) void k_scores(const int* __restrict__ mask,
                                                float* __restrict__ attn) {
    extern __shared__ __align__(16) char sm[];
    const int tid = threadIdx.x, lane = tid & 31, wid = tid >> 5;
    const int wm = wid & 3, wn = wid >> 2;
    const int bh = blockIdx.z, b = bh >> 4, h = bh & 15;
    const int rowBase = blockIdx.y * 128, colBase = blockIdx.x * 128;

    const int lrow = tid >> 1, hl = tid & 1;
    const __nv_bfloat16* asrc = (hl ? g_Ql : g_Qh)
        + (size_t)(b * S_ + rowBase + lrow) * HID + h * DK;
    const __nv_bfloat16* bsrc = (hl ? g_Kl : g_Kh)
        + (size_t)(b * S_ + colBase + lrow) * HID + h * DK;
    const uint32_t sb = smem_u32(sm);
    const uint32_t adst = sb + lrow * 144 + hl * 64;
    const uint32_t bdst = sb + 2 * TILE128 + lrow * 144 + hl * 64;

#pragma unroll
    for (int i = 0; i < 4; i++) {
        cpa16(adst + i * 16, asrc + i * 8);
        cpa16(bdst + i * 16, bsrc + i * 8);
    }
    CPCOMMIT();

    float c[2][8][4] = {};
    for (int ch = 0; ch < 2; ch++) {         // K = 64, chunk 32
        const int cur = ch & 1;
        if (ch < 1) {
            const int nb = cur ^ 1;
#pragma unroll
            for (int i = 0; i < 4; i++) {
                cpa16(adst + nb * TILE128 + i * 16, asrc + 32 + i * 8);
                cpa16(bdst + nb * TILE128 + i * 16, bsrc + 32 + i * 8);
            }
            CPCOMMIT();
            CPWAIT1();
        } else {
            CPWAIT0();
        }
        __syncthreads();
        mma_chunk<8, true>(c, (const __nv_bfloat16(*)[TROW])(sm + cur * TILE128),
                           (const __nv_bfloat16(*)[TROW])(sm + (2 + cur) * TILE128),
                           wm, wn, lane);
        __syncthreads();
    }
    const int* mb = mask + (size_t)b * S_ * S_;
    float* ab = attn + (size_t)bh * S_ * S_;
#pragma unroll
    for (int mt = 0; mt < 2; mt++) {
#pragma unroll
        for (int half = 0; half < 2; half++) {
            const int r = rowBase + wm * 32 + mt * 16 + (lane >> 2) + half * 8;
#pragma unroll
            for (int nt = 0; nt < 8; nt++) {
                const int cc = colBase + wn * 64 + nt * 8 + (lane & 3) * 2;
                int2 m = *(const int2*)(mb + (size_t)r * S_ + cc);
                float2 v;
                v.x = m.x ? c[mt][nt][half * 2] * 0.125f : -1e9f;
                v.y = m.y ? c[mt][nt][half * 2 + 1] * 0.125f : -1e9f;
                *(float2*)(ab + (size_t)r * S_ + cc) = v;
            }
        }
    }
}

// ---------------------------------------------------------------------------
// Context (plain): ctx[q,d] = sum_k attn16[q,k] * Vt16[bh][d][k]. grid (16,1,32)
// ---------------------------------------------------------------------------
__global__ __launch_bounds__(256) void k_context() {
    extern __shared__ __align__(16) char sm[];
    const int tid = threadIdx.x, lane = tid & 31, wid = tid >> 5;
    const int wm = wid & 3, wn = wid >> 2;
    const int bh = blockIdx.z, b = bh >> 4, h = bh & 15;
    const int rowBase = blockIdx.x * 128;

    const int lrow = tid >> 1, hf = tid & 1;
    const int bd = tid >> 2, bq = tid & 3;
    const __nv_bfloat16* asrc = g_attn16
        + ((size_t)bh * S_ + rowBase + lrow) * S_ + hf * 32;
    const __nv_bfloat16* bsrc = g_Vt16 + ((size_t)bh * DK + bd) * S_ + bq * 16;
    const uint32_t sb = smem_u32(sm);
    const uint32_t adst = sb + lrow * 144 + hf * 64;
    const uint32_t bdst = sb + 2 * TILE128 + bd * 144 + bq * 32;

#pragma unroll
    for (int i = 0; i < 4; i++) cpa16(adst + i * 16, asrc + i * 8);
    cpa16(bdst, bsrc);
    cpa16(bdst + 16, bsrc + 8);
    CPCOMMIT();

    float c[2][4][4] = {};
    for (int ch = 0; ch < 32; ch++) {        // K = 2048, chunk 64
        const int cur = ch & 1;
        if (ch < 31) {
            const int nb = cur ^ 1;
            const __nv_bfloat16* a = asrc + (ch + 1) * 64;
            const __nv_bfloat16* bb = bsrc + (ch + 1) * 64;
#pragma unroll
            for (int i = 0; i < 4; i++) cpa16(adst + nb * TILE128 + i * 16, a + i * 8);
            cpa16(bdst + nb * TILE64, bb);
            cpa16(bdst + nb * TILE64 + 16, bb + 8);
            CPCOMMIT();
            CPWAIT1();
        } else {
            CPWAIT0();
        }
        __syncthreads();
        mma_chunk<4, false>(c, (const __nv_bfloat16(*)[TROW])(sm + cur * TILE128),
                            (const __nv_bfloat16(*)[TROW])(sm + 2 * TILE128 + cur * TILE64),
                            wm, wn, lane);
        __syncthreads();
    }
#pragma unroll
    for (int mt = 0; mt < 2; mt++) {
#pragma unroll
        for (int half = 0; half < 2; half++) {
            const int q = rowBase + wm * 32 + mt * 16 + (lane >> 2) + half * 8;
#pragma unroll
            for (int nt = 0; nt < 4; nt++) {
                const int d = wn * 32 + nt * 8 + (lane & 3) * 2;
                __nv_bfloat16 v0 = __float2bfloat16(c[mt][nt][half * 2]);
                __nv_bfloat16 v1 = __float2bfloat16(c[mt][nt][half * 2 + 1]);
                uint32_t w = (uint32_t)__bfloat16_as_ushort(v0) |
                             ((uint32_t)__bfloat16_as_ushort(v1) << 16);
                *(uint32_t*)(g_ctx16 + ((size_t)b * S_ + q) * HID + h * DK + d) = w;
            }
        }
    }
}

// ---------------------------------------------------------------------------
// O projection (plain) + residual: tmp = ctx16 @ Wo16^T + x.  grid (8, 32)
// ---------------------------------------------------------------------------
__global__ __launch_bounds__(256) void k_oproj(const float* __restrict__ x) {
    extern __shared__ __align__(16) char sm[];
    const int tid = threadIdx.x, lane = tid & 31, wid = tid >> 5;
    const int wm = wid & 3, wn = wid >> 2;
    const int rowBase = blockIdx.y * 128, colBase = blockIdx.x * 128;

    const int lrow = tid >> 1, hf = tid & 1;
    const __nv_bfloat16* asrc = g_ctx16 + (size_t)(rowBase + lrow) * HID + hf * 32;
    const __nv_bfloat16* bsrc = g_Woh + (size_t)(colBase + lrow) * HID + hf * 32;
    const uint32_t sb = smem_u32(sm);
    const uint32_t adst = sb + lrow * 144 + hf * 64;
    const uint32_t bdst = sb + 2 * TILE128 + lrow * 144 + hf * 64;

#pragma unroll
    for (int i = 0; i < 4; i++) {
        cpa16(adst + i * 16, asrc + i * 8);
        cpa16(bdst + i * 16, bsrc + i * 8);
    }
    CPCOMMIT();

    float c[2][8][4] = {};
    for (int ch = 0; ch < 16; ch++) {        // K = 1024, chunk 64
        const int cur = ch & 1;
        if (ch < 15) {
            const int nb = cur ^ 1;
            const __nv_bfloat16* a = asrc + (ch + 1) * 64;
            const __nv_bfloat16* b = bsrc + (ch + 1) * 64;
#pragma unroll
            for (int i = 0; i < 4; i++) {
                cpa16(adst + nb * TILE128 + i * 16, a + i * 8);
                cpa16(bdst + nb * TILE128 + i * 16, b + i * 8);
            }
            CPCOMMIT();
            CPWAIT1();
        } else {
            CPWAIT0();
        }
        __syncthreads();
        mma_chunk<8, false>(c, (const __nv_bfloat16(*)[TROW])(sm + cur * TILE128),
                            (const __nv_bfloat16(*)[TROW])(sm + (2 + cur) * TILE128),
                            wm, wn, lane);
        __syncthreads();
    }
#pragma unroll
    for (int mt = 0; mt < 2; mt++) {
#pragma unroll
        for (int half = 0; half < 2; half++) {
            const int r = rowBase + wm * 32 + mt * 16 + (lane >> 2) + half * 8;
#pragma unroll
            for (int nt = 0; nt < 8; nt++) {
                const int cc = colBase + wn * 64 + nt * 8 + (lane & 3) * 2;
                float2 q = *(const float2*)(x + (size_t)r * HID + cc);
                float2 v = make_float2(c[mt][nt][half * 2] + q.x,
                                       c[mt][nt][half * 2 + 1] + q.y);
                *(float2*)(g_tmp + (size_t)r * HID + cc) = v;
            }
        }
    }
}

// ---------------------------------------------------------------------------
// Softmax: in-place fp32 normalize + bf16 copy.  grid = B*NH*S rows.
// ---------------------------------------------------------------------------
__device__ __forceinline__ float blockReduceMax(float v) {
    __shared__ float s[8];
    const int lane = threadIdx.x & 31, wid = threadIdx.x >> 5;
#pragma unroll
    for (int o = 16; o > 0; o >>= 1) v = fmaxf(v, __shfl_xor_sync(0xffffffffu, v, o));
    __syncthreads();
    if (lane == 0) s[wid] = v;
    __syncthreads();
    float r = s[0];
#pragma unroll
    for (int i = 1; i < 8; i++) r = fmaxf(r, s[i]);
    return r;
}
__device__ __forceinline__ float blockReduceSum(float v) {
    __shared__ float s[8];
    const int lane = threadIdx.x & 31, wid = threadIdx.x >> 5;
#pragma unroll
    for (int o = 16; o > 0; o >>= 1) v += __shfl_xor_sync(0xffffffffu, v, o);
    __syncthreads();
    if (lane == 0) s[wid] = v;
    __syncthreads();
    float r = s[0];
#pragma unroll
    for (int i = 1; i < 8; i++) r += s[i];
    return r;
}

__global__ __launch_bounds__(256) void softmax_kernel(float* __restrict__ attn) {
    const size_t row = blockIdx.x;
    float4* p = (float4*)(attn + row * (size_t)S_);
    __nv_bfloat16* p16 = g_attn16 + row * (size_t)S_;
    const int tid = threadIdx.x;
    float4 v0 = p[tid];
    float4 v1 = p[tid + 256];
    float m = fmaxf(fmaxf(fmaxf(v0.x, v0.y), fmaxf(v0.z, v0.w)),
                    fmaxf(fmaxf(v1.x, v1.y), fmaxf(v1.z, v1.w)));
    m = blockReduceMax(m);
    float4 e0, e1;
    e0.x = __expf(v0.x - m); e0.y = __expf(v0.y - m);
    e0.z = __expf(v0.z - m); e0.w = __expf(v0.w - m);
    e1.x = __expf(v1.x - m); e1.y = __expf(v1.y - m);
    e1.z = __expf(v1.z - m); e1.w = __expf(v1.w - m);
    float s = e0.x + e0.y + e0.z + e0.w + e1.x + e1.y + e1.z + e1.w;
    s = blockReduceSum(s);
    float inv = 1.0f / s;
    e0.x *= inv; e0.y *= inv; e0.z *= inv; e0.w *= inv;
    e1.x *= inv; e1.y *= inv; e1.z *= inv; e1.w *= inv;
    p[tid] = e0;
    p[tid + 256] = e1;
    uint2 w0, w1;
    w0.x = (uint32_t)__bfloat16_as_ushort(__float2bfloat16(e0.x)) |
           ((uint32_t)__bfloat16_as_ushort(__float2bfloat16(e0.y)) << 16);
    w0.y = (uint32_t)__bfloat16_as_ushort(__float2bfloat16(e0.z)) |
           ((uint32_t)__bfloat16_as_ushort(__float2bfloat16(e0.w)) << 16);
    w1.x = (uint32_t)__bfloat16_as_ushort(__float2bfloat16(e1.x)) |
           ((uint32_t)__bfloat16_as_ushort(__float2bfloat16(e1.y)) << 16);
    w1.y = (uint32_t)__bfloat16_as_ushort(__float2bfloat16(e1.z)) |
           ((uint32_t)__bfloat16_as_ushort(__float2bfloat16(e1.w)) << 16);
    *(uint2*)(p16 + (size_t)tid * 4) = w0;
    *(uint2*)(p16 + (size_t)(tid + 256) * 4) = w1;
}

__global__ __launch_bounds__(256) void ln_kernel(const float* __restrict__ x,
                                                 float* __restrict__ out) {
    const size_t row = blockIdx.x;
    const float4* p = (const float4*)(x + row * HID);
    const int tid = threadIdx.x;
    float4 v = p[tid];
    float s = v.x + v.y + v.z + v.w;
    s = blockReduceSum(s);
    const float mu = s * (1.0f / HID);
    float dx = v.x - mu, dy = v.y - mu, dz = v.z - mu, dw = v.w - mu;
    float sq = dx * dx + dy * dy + dz * dz + dw * dw;
    sq = blockReduceSum(sq);
    const float inv = rsqrtf(sq * (1.0f / HID) + 1e-5f);
    float4 o;
    o.x = dx * inv; o.y = dy * inv; o.z = dz * inv; o.w = dw * inv;
    ((float4*)(out + row * HID))[tid] = o;
}

// ===========================================================================
extern "C" void kernel_launch(void* const* d_in, const int* in_sizes, int n_in,
                              void* d_out, int out_size)
{
    (void)in_sizes; (void)n_in; (void)out_size;
    const float* x  = (const float*)d_in[0];
    const int* mask = (const int*)d_in[1];
    const float* Wq = (const float*)d_in[2];
    const float* Wk = (const float*)d_in[3];
    const float* Wv = (const float*)d_in[4];
    const float* Wo = (const float*)d_in[5];
    float* out  = (float*)d_out;
    float* attn = out + OUT_ELEMS;

    __nv_bfloat16 *pXh, *pXl, *pWqh, *pWql, *pWkh, *pWkl, *pWvh, *pWoh;
    float* ptmp;
    cudaGetSymbolAddress((void**)&pXh,  g_Xh);
    cudaGetSymbolAddress((void**)&pXl,  g_Xl);
    cudaGetSymbolAddress((void**)&pWqh, g_Wqh);
    cudaGetSymbolAddress((void**)&pWql, g_Wql);
    cudaGetSymbolAddress((void**)&pWkh, g_Wkh);
    cudaGetSymbolAddress((void**)&pWkl, g_Wkl);
    cudaGetSymbolAddress((void**)&pWvh, g_Wvh);
    cudaGetSymbolAddress((void**)&pWoh, g_Woh);
    cudaGetSymbolAddress((void**)&ptmp, g_tmp);

    cudaFuncSetAttribute(k_proj_qk, cudaFuncAttributeMaxDynamicSharedMemorySize, SMEM_GEMM);
    cudaFuncSetAttribute(k_proj_v,  cudaFuncAttributeMaxDynamicSharedMemorySize, SMEM_GEMM);
    cudaFuncSetAttribute(k_scores,  cudaFuncAttributeMaxDynamicSharedMemorySize, SMEM_GEMM);
    cudaFuncSetAttribute(k_context, cudaFuncAttributeMaxDynamicSharedMemorySize, SMEM_CTX);
    cudaFuncSetAttribute(k_oproj,   cudaFuncAttributeMaxDynamicSharedMemorySize, SMEM_GEMM);

    dim3 blk(256);

    // Pre-conversions
    k_cvt<<<dim3((ROWS * HID / 4 + 255) / 256), blk>>>(x,  pXh,  pXl,  ROWS * HID / 4);
    k_cvt<<<dim3((HID * HID / 4 + 255) / 256), blk>>>(Wq, pWqh, pWql, HID * HID / 4);
    k_cvt<<<dim3((HID * HID / 4 + 255) / 256), blk>>>(Wk, pWkh, pWkl, HID * HID / 4);
    k_cvt<<<dim3((HID * HID / 4 + 255) / 256), blk>>>(Wv, pWvh, nullptr, HID * HID / 4);
    k_cvt<<<dim3((HID * HID / 4 + 255) / 256), blk>>>(Wo, pWoh, nullptr, HID * HID / 4);

    // Projections
    k_proj_qk<<<dim3(HID / 128, ROWS / 128, 2), blk, SMEM_GEMM>>>();
    k_proj_v <<<dim3(HID / 128, ROWS / 128),    blk, SMEM_GEMM>>>();

    // Scores -> raw attn
    k_scores<<<dim3(S_ / 128, S_ / 128, B_ * NH), blk, SMEM_GEMM>>>(mask, attn);

    // Softmax (fp32 in place + bf16 copy)
    softmax_kernel<<<dim3(B_ * NH * S_), blk>>>(attn);

    // Context
    k_context<<<dim3(S_ / 128, 1, B_ * NH), blk, SMEM_CTX>>>();

    // O projection + residual
    k_oproj<<<dim3(HID / 128, ROWS / 128), blk, SMEM_GEMM>>>(x);

    // LayerNorm
    ln_kernel<<<dim3(ROWS), blk>>>(ptmp, out);
}

// round 8
// speedup vs baseline: 1.6446x; 1.1592x over previous
#include <cuda_runtime.h>
#include <cuda_bf16.h>
#include <cuda_fp16.h>
#include <cstdint>
#include <math.h>

#define B_   2
#define S_   2048
#define NH   16
#define DK   64
#define HID  1024
#define ROWS (B_ * S_)          // 4096

static const size_t OUT_ELEMS = (size_t)ROWS * HID;   // 4,194,304

// ---------------------------------------------------------------------------
// Scratch (__device__ globals; no allocation allowed)
// ---------------------------------------------------------------------------
__device__ __nv_bfloat16 g_Xh [(size_t)ROWS * HID];
__device__ __nv_bfloat16 g_Xl [(size_t)ROWS * HID];
__device__ __nv_bfloat16 g_Wqh[(size_t)HID * HID];
__device__ __nv_bfloat16 g_Wql[(size_t)HID * HID];
__device__ __nv_bfloat16 g_Wkh[(size_t)HID * HID];
__device__ __nv_bfloat16 g_Wkl[(size_t)HID * HID];
__device__ __nv_bfloat16 g_Wvh[(size_t)HID * HID];
__device__ __nv_bfloat16 g_Woh[(size_t)HID * HID];
__device__ __half        g_Qf [(size_t)ROWS * HID];
__device__ __half        g_Kf [(size_t)ROWS * HID];
__device__ __nv_bfloat16 g_Vt16[(size_t)B_ * NH * DK * S_];          // [bh][d][k]
__device__ __nv_bfloat16 g_attn16[(size_t)B_ * NH * S_ * S_];        // 268 MB
__device__ __nv_bfloat16 g_ctx16[(size_t)ROWS * HID];
__device__ float         g_tmp [(size_t)ROWS * HID];

// Tile geometry: row = 72 halves (144 B) -> conflict-free ldmatrix phases.
#define TROW    72
#define TILE128 (128 * TROW * 2)   // 18432
#define TILE64  (64 * TROW * 2)    // 9216
#define SMEM_GEMM (4 * TILE128)                 // 73728: A0,A1,B0,B1
#define SMEM_CTX  (2 * TILE128 + 2 * TILE64)    // 55296

// ---------------------------------------------------------------------------
// PTX helpers
// ---------------------------------------------------------------------------
__device__ __forceinline__ uint32_t smem_u32(const void* p) {
    uint32_t a;
    asm("{ .reg .u64 t; cvta.to.shared.u64 t, %1; cvt.u32.u64 %0, t; }"
        : "=r"(a) : "l"(p));
    return a;
}
__device__ __forceinline__ void cpa16(uint32_t dst, const void* src) {
    asm volatile("cp.async.cg.shared.global [%0], [%1], 16;"
                 :: "r"(dst), "l"(__cvta_generic_to_global(src)));
}
#define CPCOMMIT() asm volatile("cp.async.commit_group;" ::: "memory")
#define CPWAIT1()  asm volatile("cp.async.wait_group 1;" ::: "memory")
#define CPWAIT0()  asm volatile("cp.async.wait_group 0;" ::: "memory")

__device__ __forceinline__ void ldsm_x4(uint32_t (&r)[4], uint32_t addr) {
    asm volatile("ldmatrix.sync.aligned.m8n8.x4.shared.b16 {%0,%1,%2,%3}, [%4];"
                 : "=r"(r[0]), "=r"(r[1]), "=r"(r[2]), "=r"(r[3]) : "r"(addr));
}
__device__ __forceinline__ void mma_bf16(float (&c)[4], const uint32_t (&a)[4],
                                         uint32_t b0, uint32_t b1) {
    asm volatile(
        "mma.sync.aligned.m16n8k16.row.col.f32.bf16.bf16.f32 "
        "{%0,%1,%2,%3}, {%4,%5,%6,%7}, {%8,%9}, {%0,%1,%2,%3};"
        : "+f"(c[0]), "+f"(c[1]), "+f"(c[2]), "+f"(c[3])
        : "r"(a[0]), "r"(a[1]), "r"(a[2]), "r"(a[3]), "r"(b0), "r"(b1));
}
__device__ __forceinline__ void mma_f16(float (&c)[4], const uint32_t (&a)[4],
                                        uint32_t b0, uint32_t b1) {
    asm volatile(
        "mma.sync.aligned.m16n8k16.row.col.f32.f16.f16.f32 "
        "{%0,%1,%2,%3}, {%4,%5,%6,%7}, {%8,%9}, {%0,%1,%2,%3};"
        : "+f"(c[0]), "+f"(c[1]), "+f"(c[2]), "+f"(c[3])
        : "r"(a[0]), "r"(a[1]), "r"(a[2]), "r"(a[3]), "r"(b0), "r"(b1));
}

// One K-chunk of MMAs.
// SPLIT (bf16): cols [0..31]=hi, [32..63]=lo, 2 k16 steps, hi*hi+hi*lo+lo*hi.
// PLAIN: cols [0..63], 4 k16 steps, 1 term (bf16 or f16 via F16 flag).
template <int NT, bool SPLIT, bool F16>
__device__ __forceinline__ void mma_chunk(float (*cacc)[NT][4],
                                          const __nv_bfloat16 (*As)[TROW],
                                          const __nv_bfloat16 (*Bs)[TROW],
                                          int wm, int wn, int lane) {
    const int NS = SPLIT ? 2 : 4;
#pragma unroll
    for (int s = 0; s < NS; s++) {
        uint32_t ah[2][4], al[2][4];
#pragma unroll
        for (int mt = 0; mt < 2; mt++) {
            const int r = wm * 32 + mt * 16 + (lane & 15);
            const int cc = s * 16 + ((lane >> 4) << 3);
            ldsm_x4(ah[mt], smem_u32(&As[r][cc]));
            if (SPLIT) ldsm_x4(al[mt], smem_u32(&As[r][cc + 32]));
        }
#pragma unroll
        for (int g = 0; g < NT / 2; g++) {
            const int br = wn * (NT * 8) + g * 16 + (lane & 15);
            const int bc = s * 16 + ((lane >> 4) << 3);
            uint32_t bh[4], bl[4];
            ldsm_x4(bh, smem_u32(&Bs[br][bc]));
            if (SPLIT) ldsm_x4(bl, smem_u32(&Bs[br][bc + 32]));
#pragma unroll
            for (int mt = 0; mt < 2; mt++) {
                if (F16) {
                    mma_f16(cacc[mt][2 * g],     ah[mt], bh[0], bh[2]);
                    mma_f16(cacc[mt][2 * g + 1], ah[mt], bh[1], bh[3]);
                } else {
                    mma_bf16(cacc[mt][2 * g],     ah[mt], bh[0], bh[2]);
                    mma_bf16(cacc[mt][2 * g + 1], ah[mt], bh[1], bh[3]);
                }
                if (SPLIT) {
                    mma_bf16(cacc[mt][2 * g],     ah[mt], bl[0], bl[2]);
                    mma_bf16(cacc[mt][2 * g + 1], ah[mt], bl[1], bl[3]);
                    mma_bf16(cacc[mt][2 * g],     al[mt], bh[0], bh[2]);
                    mma_bf16(cacc[mt][2 * g + 1], al[mt], bh[1], bh[3]);
                }
            }
        }
    }
}

// ---------------------------------------------------------------------------
// Merged conversion kernel: X -> split, Wq/Wk -> split, Wv/Wo -> plain.
// Each item = 4 floats.  grid covers N_X + 4*N_W items.
// ---------------------------------------------------------------------------
#define N_X4 (ROWS * HID / 4)      // 1,048,576
#define N_W4 (HID * HID / 4)       //   262,144

__device__ __forceinline__ void cvt4(const float* __restrict__ s, size_t i,
                                     __nv_bfloat16* __restrict__ dh,
                                     __nv_bfloat16* __restrict__ dl) {
    float4 v = ((const float4*)s)[i];
    __nv_bfloat16 h0 = __float2bfloat16(v.x), h1 = __float2bfloat16(v.y);
    __nv_bfloat16 h2 = __float2bfloat16(v.z), h3 = __float2bfloat16(v.w);
    uint2 hw;
    hw.x = (uint32_t)__bfloat16_as_ushort(h0) | ((uint32_t)__bfloat16_as_ushort(h1) << 16);
    hw.y = (uint32_t)__bfloat16_as_ushort(h2) | ((uint32_t)__bfloat16_as_ushort(h3) << 16);
    *(uint2*)(dh + i * 4) = hw;
    if (dl) {
        __nv_bfloat16 l0 = __float2bfloat16(v.x - __bfloat162float(h0));
        __nv_bfloat16 l1 = __float2bfloat16(v.y - __bfloat162float(h1));
        __nv_bfloat16 l2 = __float2bfloat16(v.z - __bfloat162float(h2));
        __nv_bfloat16 l3 = __float2bfloat16(v.w - __bfloat162float(h3));
        uint2 lw;
        lw.x = (uint32_t)__bfloat16_as_ushort(l0) | ((uint32_t)__bfloat16_as_ushort(l1) << 16);
        lw.y = (uint32_t)__bfloat16_as_ushort(l2) | ((uint32_t)__bfloat16_as_ushort(l3) << 16);
        *(uint2*)(dl + i * 4) = lw;
    }
}

__global__ __launch_bounds__(256) void k_cvt_all(const float* __restrict__ x,
                                                 const float* __restrict__ Wq,
                                                 const float* __restrict__ Wk,
                                                 const float* __restrict__ Wv,
                                                 const float* __restrict__ Wo) {
    const size_t i = (size_t)blockIdx.x * 256 + threadIdx.x;
    if (i < N_X4) {
        cvt4(x, i, g_Xh, g_Xl);
        return;
    }
    const size_t j = i - N_X4;
    const int w = (int)(j >> 18);        // N_W4 = 2^18
    const size_t k = j & (N_W4 - 1);
    if (w == 0)      cvt4(Wq, k, g_Wqh, g_Wql);
    else if (w == 1) cvt4(Wk, k, g_Wkh, g_Wkl);
    else if (w == 2) cvt4(Wv, k, g_Wvh, nullptr);
    else             cvt4(Wo, k, g_Woh, nullptr);
}

// ---------------------------------------------------------------------------
// Q/K projection (split-bf16 input): C = X @ W^T, epilogue -> fp16 Q/K.
// grid (8, 32, 2): z=0 -> Q, z=1 -> K.
// ---------------------------------------------------------------------------
__global__ __launch_bounds__(256) void k_proj_qk() {
    extern __shared__ __align__(16) char sm[];
    const int tid = threadIdx.x, lane = tid & 31, wid = tid >> 5;
    const int wm = wid & 3, wn = wid >> 2;
    const int z = blockIdx.z;
    const int rowBase = blockIdx.y * 128, colBase = blockIdx.x * 128;
    const __nv_bfloat16* Bh = z ? g_Wkh : g_Wqh;
    const __nv_bfloat16* Bl = z ? g_Wkl : g_Wql;
    __half* Of = z ? g_Kf : g_Qf;

    const int lrow = tid >> 1, hl = tid & 1;
    const __nv_bfloat16* asrc = (hl ? g_Xl : g_Xh) + (size_t)(rowBase + lrow) * HID;
    const __nv_bfloat16* bsrc = (hl ? Bl : Bh) + (size_t)(colBase + lrow) * HID;
    const uint32_t sb = smem_u32(sm);
    const uint32_t adst = sb + lrow * 144 + hl * 64;
    const uint32_t bdst = sb + 2 * TILE128 + lrow * 144 + hl * 64;

#pragma unroll
    for (int i = 0; i < 4; i++) {
        cpa16(adst + i * 16, asrc + i * 8);
        cpa16(bdst + i * 16, bsrc + i * 8);
    }
    CPCOMMIT();

    float c[2][8][4] = {};
    for (int ch = 0; ch < 32; ch++) {
        const int cur = ch & 1;
        if (ch < 31) {
            const int nb = cur ^ 1;
            const __nv_bfloat16* a = asrc + (ch + 1) * 32;
            const __nv_bfloat16* b = bsrc + (ch + 1) * 32;
#pragma unroll
            for (int i = 0; i < 4; i++) {
                cpa16(adst + nb * TILE128 + i * 16, a + i * 8);
                cpa16(bdst + nb * TILE128 + i * 16, b + i * 8);
            }
            CPCOMMIT();
            CPWAIT1();
        } else {
            CPWAIT0();
        }
        __syncthreads();
        mma_chunk<8, true, false>(c, (const __nv_bfloat16(*)[TROW])(sm + cur * TILE128),
                                  (const __nv_bfloat16(*)[TROW])(sm + (2 + cur) * TILE128),
                                  wm, wn, lane);
        __syncthreads();
    }
#pragma unroll
    for (int mt = 0; mt < 2; mt++) {
#pragma unroll
        for (int half = 0; half < 2; half++) {
            const int r = rowBase + wm * 32 + mt * 16 + (lane >> 2) + half * 8;
#pragma unroll
            for (int nt = 0; nt < 8; nt++) {
                const int cc = colBase + wn * 64 + nt * 8 + (lane & 3) * 2;
                __half h0 = __float2half(c[mt][nt][half * 2]);
                __half h1 = __float2half(c[mt][nt][half * 2 + 1]);
                uint32_t w = (uint32_t)__half_as_ushort(h0) |
                             ((uint32_t)__half_as_ushort(h1) << 16);
                *(uint32_t*)(Of + (size_t)r * HID + cc) = w;
            }
        }
    }
}

// ---------------------------------------------------------------------------
// V projection (plain bf16): V = X @ Wv^T, epilogue scatters into Vt16[bh][d][k]
// grid (8, 32)
// ---------------------------------------------------------------------------
__global__ __launch_bounds__(256) void k_proj_v() {
    extern __shared__ __align__(16) char sm[];
    const int tid = threadIdx.x, lane = tid & 31, wid = tid >> 5;
    const int wm = wid & 3, wn = wid >> 2;
    const int rowBase = blockIdx.y * 128, colBase = blockIdx.x * 128;

    const int lrow = tid >> 1, hf = tid & 1;
    const __nv_bfloat16* asrc = g_Xh + (size_t)(rowBase + lrow) * HID + hf * 32;
    const __nv_bfloat16* bsrc = g_Wvh + (size_t)(colBase + lrow) * HID + hf * 32;
    const uint32_t sb = smem_u32(sm);
    const uint32_t adst = sb + lrow * 144 + hf * 64;
    const uint32_t bdst = sb + 2 * TILE128 + lrow * 144 + hf * 64;

#pragma unroll
    for (int i = 0; i < 4; i++) {
        cpa16(adst + i * 16, asrc + i * 8);
        cpa16(bdst + i * 16, bsrc + i * 8);
    }
    CPCOMMIT();

    float c[2][8][4] = {};
    for (int ch = 0; ch < 16; ch++) {        // K = 1024, chunk 64
        const int cur = ch & 1;
        if (ch < 15) {
            const int nb = cur ^ 1;
            const __nv_bfloat16* a = asrc + (ch + 1) * 64;
            const __nv_bfloat16* b = bsrc + (ch + 1) * 64;
#pragma unroll
            for (int i = 0; i < 4; i++) {
                cpa16(adst + nb * TILE128 + i * 16, a + i * 8);
                cpa16(bdst + nb * TILE128 + i * 16, b + i * 8);
            }
            CPCOMMIT();
            CPWAIT1();
        } else {
            CPWAIT0();
        }
        __syncthreads();
        mma_chunk<8, false, false>(c, (const __nv_bfloat16(*)[TROW])(sm + cur * TILE128),
                                   (const __nv_bfloat16(*)[TROW])(sm + (2 + cur) * TILE128),
                                   wm, wn, lane);
        __syncthreads();
    }
    // scatter to Vt16[bh][d][k]
#pragma unroll
    for (int mt = 0; mt < 2; mt++) {
#pragma unroll
        for (int half = 0; half < 2; half++) {
            const int r = rowBase + wm * 32 + mt * 16 + (lane >> 2) + half * 8;
            const int b = r >> 11, k = r & (S_ - 1);
#pragma unroll
            for (int nt = 0; nt < 8; nt++) {
                const int cc = colBase + wn * 64 + nt * 8 + (lane & 3) * 2;
                const int h = cc >> 6, d = cc & 63;
                const size_t base = ((size_t)(b * NH + h) * DK + d) * S_ + k;
                g_Vt16[base]      = __float2bfloat16(c[mt][nt][half * 2]);
                g_Vt16[base + S_] = __float2bfloat16(c[mt][nt][half * 2 + 1]);
            }
        }
    }
}

// ---------------------------------------------------------------------------
// Scores (plain fp16, K=64): raw = (Q_h @ K_h^T)/8, masked -> -1e9.
// grid (16,16,32).  Single smem fill, no pipeline.
// ---------------------------------------------------------------------------
__global__ __launch_bounds__(256) void k_scores(const int* __restrict__ mask,
                                                float* __restrict__ attn) {
    __shared__ __align__(16) __nv_bfloat16 As[128][TROW];
    __shared__ __align__(16) __nv_bfloat16 Bs[128][TROW];
    const int tid = threadIdx.x, lane = tid & 31, wid = tid >> 5;
    const int wm = wid & 3, wn = wid >> 2;
    const int bh = blockIdx.z, b = bh >> 4, h = bh & 15;
    const int rowBase = blockIdx.y * 128, colBase = blockIdx.x * 128;

    const int lrow = tid >> 1, hf = tid & 1;
    const __half* asrc = g_Qf + (size_t)(b * S_ + rowBase + lrow) * HID + h * DK + hf * 32;
    const __half* bsrc = g_Kf + (size_t)(b * S_ + colBase + lrow) * HID + h * DK + hf * 32;
    const uint32_t adst = smem_u32(&As[lrow][0]) + hf * 64;
    const uint32_t bdst = smem_u32(&Bs[lrow][0]) + hf * 64;

#pragma unroll
    for (int i = 0; i < 4; i++) {
        cpa16(adst + i * 16, asrc + i * 8);
        cpa16(bdst + i * 16, bsrc + i * 8);
    }
    CPCOMMIT();
    CPWAIT0();
    __syncthreads();

    float c[2][8][4] = {};
    mma_chunk<8, false, true>(c, As, Bs, wm, wn, lane);

    const int* mb = mask + (size_t)b * S_ * S_;
    float* ab = attn + (size_t)bh * S_ * S_;
#pragma unroll
    for (int mt = 0; mt < 2; mt++) {
#pragma unroll
        for (int half = 0; half < 2; half++) {
            const int r = rowBase + wm * 32 + mt * 16 + (lane >> 2) + half * 8;
#pragma unroll
            for (int nt = 0; nt < 8; nt++) {
                const int cc = colBase + wn * 64 + nt * 8 + (lane & 3) * 2;
                int2 m = *(const int2*)(mb + (size_t)r * S_ + cc);
                float2 v;
                v.x = m.x ? c[mt][nt][half * 2] * 0.125f : -1e9f;
                v.y = m.y ? c[mt][nt][half * 2 + 1] * 0.125f : -1e9f;
                *(float2*)(ab + (size_t)r * S_ + cc) = v;
            }
        }
    }
}

// ---------------------------------------------------------------------------
// Context (plain bf16): ctx[q,d] = sum_k attn16[q,k] * Vt16[bh][d][k]. grid (16,1,32)
// ---------------------------------------------------------------------------
__global__ __launch_bounds__(256) void k_context() {
    extern __shared__ __align__(16) char sm[];
    const int tid = threadIdx.x, lane = tid & 31, wid = tid >> 5;
    const int wm = wid & 3, wn = wid >> 2;
    const int bh = blockIdx.z, b = bh >> 4, h = bh & 15;
    const int rowBase = blockIdx.x * 128;

    const int lrow = tid >> 1, hf = tid & 1;
    const int bd = tid >> 2, bq = tid & 3;
    const __nv_bfloat16* asrc = g_attn16
        + ((size_t)bh * S_ + rowBase + lrow) * S_ + hf * 32;
    const __nv_bfloat16* bsrc = g_Vt16 + ((size_t)bh * DK + bd) * S_ + bq * 16;
    const uint32_t sb = smem_u32(sm);
    const uint32_t adst = sb + lrow * 144 + hf * 64;
    const uint32_t bdst = sb + 2 * TILE128 + bd * 144 + bq * 32;

#pragma unroll
    for (int i = 0; i < 4; i++) cpa16(adst + i * 16, asrc + i * 8);
    cpa16(bdst, bsrc);
    cpa16(bdst + 16, bsrc + 8);
    CPCOMMIT();

    float c[2][4][4] = {};
    for (int ch = 0; ch < 32; ch++) {        // K = 2048, chunk 64
        const int cur = ch & 1;
        if (ch < 31) {
            const int nb = cur ^ 1;
            const __nv_bfloat16* a = asrc + (ch + 1) * 64;
            const __nv_bfloat16* bb = bsrc + (ch + 1) * 64;
#pragma unroll
            for (int i = 0; i < 4; i++) cpa16(adst + nb * TILE128 + i * 16, a + i * 8);
            cpa16(bdst + nb * TILE64, bb);
            cpa16(bdst + nb * TILE64 + 16, bb + 8);
            CPCOMMIT();
            CPWAIT1();
        } else {
            CPWAIT0();
        }
        __syncthreads();
        mma_chunk<4, false, false>(c, (const __nv_bfloat16(*)[TROW])(sm + cur * TILE128),
                                   (const __nv_bfloat16(*)[TROW])(sm + 2 * TILE128 + cur * TILE64),
                                   wm, wn, lane);
        __syncthreads();
    }
#pragma unroll
    for (int mt = 0; mt < 2; mt++) {
#pragma unroll
        for (int half = 0; half < 2; half++) {
            const int q = rowBase + wm * 32 + mt * 16 + (lane >> 2) + half * 8;
#pragma unroll
            for (int nt = 0; nt < 4; nt++) {
                const int d = wn * 32 + nt * 8 + (lane & 3) * 2;
                __nv_bfloat16 v0 = __float2bfloat16(c[mt][nt][half * 2]);
                __nv_bfloat16 v1 = __float2bfloat16(c[mt][nt][half * 2 + 1]);
                uint32_t w = (uint32_t)__bfloat16_as_ushort(v0) |
                             ((uint32_t)__bfloat16_as_ushort(v1) << 16);
                *(uint32_t*)(g_ctx16 + ((size_t)b * S_ + q) * HID + h * DK + d) = w;
            }
        }
    }
}

// ---------------------------------------------------------------------------
// O projection (plain bf16) + residual: tmp = ctx16 @ Wo16^T + x.  grid (8, 32)
// ---------------------------------------------------------------------------
__global__ __launch_bounds__(256) void k_oproj(const float* __restrict__ x) {
    extern __shared__ __align__(16) char sm[];
    const int tid = threadIdx.x, lane = tid & 31, wid = tid >> 5;
    const int wm = wid & 3, wn = wid >> 2;
    const int rowBase = blockIdx.y * 128, colBase = blockIdx.x * 128;

    const int lrow = tid >> 1, hf = tid & 1;
    const __nv_bfloat16* asrc = g_ctx16 + (size_t)(rowBase + lrow) * HID + hf * 32;
    const __nv_bfloat16* bsrc = g_Woh + (size_t)(colBase + lrow) * HID + hf * 32;
    const uint32_t sb = smem_u32(sm);
    const uint32_t adst = sb + lrow * 144 + hf * 64;
    const uint32_t bdst = sb + 2 * TILE128 + lrow * 144 + hf * 64;

#pragma unroll
    for (int i = 0; i < 4; i++) {
        cpa16(adst + i * 16, asrc + i * 8);
        cpa16(bdst + i * 16, bsrc + i * 8);
    }
    CPCOMMIT();

    float c[2][8][4] = {};
    for (int ch = 0; ch < 16; ch++) {        // K = 1024, chunk 64
        const int cur = ch & 1;
        if (ch < 15) {
            const int nb = cur ^ 1;
            const __nv_bfloat16* a = asrc + (ch + 1) * 64;
            const __nv_bfloat16* b = bsrc + (ch + 1) * 64;
#pragma unroll
            for (int i = 0; i < 4; i++) {
                cpa16(adst + nb * TILE128 + i * 16, a + i * 8);
                cpa16(bdst + nb * TILE128 + i * 16, b + i * 8);
            }
            CPCOMMIT();
            CPWAIT1();
        } else {
            CPWAIT0();
        }
        __syncthreads();
        mma_chunk<8, false, false>(c, (const __nv_bfloat16(*)[TROW])(sm + cur * TILE128),
                                   (const __nv_bfloat16(*)[TROW])(sm + (2 + cur) * TILE128),
                                   wm, wn, lane);
        __syncthreads();
    }
#pragma unroll
    for (int mt = 0; mt < 2; mt++) {
#pragma unroll
        for (int half = 0; half < 2; half++) {
            const int r = rowBase + wm * 32 + mt * 16 + (lane >> 2) + half * 8;
#pragma unroll
            for (int nt = 0; nt < 8; nt++) {
                const int cc = colBase + wn * 64 + nt * 8 + (lane & 3) * 2;
                float2 q = *(const float2*)(x + (size_t)r * HID + cc);
                float2 v = make_float2(c[mt][nt][half * 2] + q.x,
                                       c[mt][nt][half * 2 + 1] + q.y);
                *(float2*)(g_tmp + (size_t)r * HID + cc) = v;
            }
        }
    }
}

// ---------------------------------------------------------------------------
// Softmax: in-place fp32 normalize + bf16 copy.  grid = B*NH*S rows.
// ---------------------------------------------------------------------------
__device__ __forceinline__ float blockReduceMax(float v) {
    __shared__ float s[8];
    const int lane = threadIdx.x & 31, wid = threadIdx.x >> 5;
#pragma unroll
    for (int o = 16; o > 0; o >>= 1) v = fmaxf(v, __shfl_xor_sync(0xffffffffu, v, o));
    __syncthreads();
    if (lane == 0) s[wid] = v;
    __syncthreads();
    float r = s[0];
#pragma unroll
    for (int i = 1; i < 8; i++) r = fmaxf(r, s[i]);
    return r;
}
__device__ __forceinline__ float blockReduceSum(float v) {
    __shared__ float s[8];
    const int lane = threadIdx.x & 31, wid = threadIdx.x >> 5;
#pragma unroll
    for (int o = 16; o > 0; o >>= 1) v += __shfl_xor_sync(0xffffffffu, v, o);
    __syncthreads();
    if (lane == 0) s[wid] = v;
    __syncthreads();
    float r = s[0];
#pragma unroll
    for (int i = 1; i < 8; i++) r += s[i];
    return r;
}

__global__ __launch_bounds__(256) void softmax_kernel(float* __restrict__ attn) {
    const size_t row = blockIdx.x;
    float4* p = (float4*)(attn + row * (size_t)S_);
    __nv_bfloat16* p16 = g_attn16 + row * (size_t)S_;
    const int tid = threadIdx.x;
    float4 v0 = p[tid];
    float4 v1 = p[tid + 256];
    float m = fmaxf(fmaxf(fmaxf(v0.x, v0.y), fmaxf(v0.z, v0.w)),
                    fmaxf(fmaxf(v1.x, v1.y), fmaxf(v1.z, v1.w)));
    m = blockReduceMax(m);
    float4 e0, e1;
    e0.x = __expf(v0.x - m); e0.y = __expf(v0.y - m);
    e0.z = __expf(v0.z - m); e0.w = __expf(v0.w - m);
    e1.x = __expf(v1.x - m); e1.y = __expf(v1.y - m);
    e1.z = __expf(v1.z - m); e1.w = __expf(v1.w - m);
    float s = e0.x + e0.y + e0.z + e0.w + e1.x + e1.y + e1.z + e1.w;
    s = blockReduceSum(s);
    float inv = 1.0f / s;
    e0.x *= inv; e0.y *= inv; e0.z *= inv; e0.w *= inv;
    e1.x *= inv; e1.y *= inv; e1.z *= inv; e1.w *= inv;
    p[tid] = e0;
    p[tid + 256] = e1;
    uint2 w0, w1;
    w0.x = (uint32_t)__bfloat16_as_ushort(__float2bfloat16(e0.x)) |
           ((uint32_t)__bfloat16_as_ushort(__float2bfloat16(e0.y)) << 16);
    w0.y = (uint32_t)__bfloat16_as_ushort(__float2bfloat16(e0.z)) |
           ((uint32_t)__bfloat16_as_ushort(__float2bfloat16(e0.w)) << 16);
    w1.x = (uint32_t)__bfloat16_as_ushort(__float2bfloat16(e1.x)) |
           ((uint32_t)__bfloat16_as_ushort(__float2bfloat16(e1.y)) << 16);
    w1.y = (uint32_t)__bfloat16_as_ushort(__float2bfloat16(e1.z)) |
           ((uint32_t)__bfloat16_as_ushort(__float2bfloat16(e1.w)) << 16);
    *(uint2*)(p16 + (size_t)tid * 4) = w0;
    *(uint2*)(p16 + (size_t)(tid + 256) * 4) = w1;
}

__global__ __launch_bounds__(256) void ln_kernel(const float* __restrict__ x,
                                                 float* __restrict__ out) {
    const size_t row = blockIdx.x;
    const float4* p = (const float4*)(x + row * HID);
    const int tid = threadIdx.x;
    float4 v = p[tid];
    float s = v.x + v.y + v.z + v.w;
    s = blockReduceSum(s);
    const float mu = s * (1.0f / HID);
    float dx = v.x - mu, dy = v.y - mu, dz = v.z - mu, dw = v.w - mu;
    float sq = dx * dx + dy * dy + dz * dz + dw * dw;
    sq = blockReduceSum(sq);
    const float inv = rsqrtf(sq * (1.0f / HID) + 1e-5f);
    float4 o;
    o.x = dx * inv; o.y = dy * inv; o.z = dz * inv; o.w = dw * inv;
    ((float4*)(out + row * HID))[tid] = o;
}

// ===========================================================================
extern "C" void kernel_launch(void* const* d_in, const int* in_sizes, int n_in,
                              void* d_out, int out_size)
{
    (void)in_sizes; (void)n_in; (void)out_size;
    const float* x  = (const float*)d_in[0];
    const int* mask = (const int*)d_in[1];
    const float* Wq = (const float*)d_in[2];
    const float* Wk = (const float*)d_in[3];
    const float* Wv = (const float*)d_in[4];
    const float* Wo = (const float*)d_in[5];
    float* out  = (float*)d_out;
    float* attn = out + OUT_ELEMS;

    float* ptmp;
    cudaGetSymbolAddress((void**)&ptmp, g_tmp);

    cudaFuncSetAttribute(k_proj_qk, cudaFuncAttributeMaxDynamicSharedMemorySize, SMEM_GEMM);
    cudaFuncSetAttribute(k_proj_v,  cudaFuncAttributeMaxDynamicSharedMemorySize, SMEM_GEMM);
    cudaFuncSetAttribute(k_context, cudaFuncAttributeMaxDynamicSharedMemorySize, SMEM_CTX);
    cudaFuncSetAttribute(k_oproj,   cudaFuncAttributeMaxDynamicSharedMemorySize, SMEM_GEMM);

    dim3 blk(256);

    // Merged pre-conversions (X split, Wq/Wk split, Wv/Wo plain)
    k_cvt_all<<<dim3((N_X4 + 4 * N_W4) / 256), blk>>>(x, Wq, Wk, Wv, Wo);

    // Projections
    k_proj_qk<<<dim3(HID / 128, ROWS / 128, 2), blk, SMEM_GEMM>>>();
    k_proj_v <<<dim3(HID / 128, ROWS / 128),    blk, SMEM_GEMM>>>();

    // Scores -> raw attn (plain fp16 HMMA)
    k_scores<<<dim3(S_ / 128, S_ / 128, B_ * NH), blk>>>(mask, attn);

    // Softmax (fp32 in place + bf16 copy)
    softmax_kernel<<<dim3(B_ * NH * S_), blk>>>(attn);

    // Context
    k_context<<<dim3(S_ / 128, 1, B_ * NH), blk, SMEM_CTX>>>();

    // O projection + residual
    k_oproj<<<dim3(HID / 128, ROWS / 128), blk, SMEM_GEMM>>>(x);

    // LayerNorm
    ln_kernel<<<dim3(ROWS), blk>>>(ptmp, out);
}